// round 12
// baseline (speedup 1.0000x reference)
#include <cuda_runtime.h>
#include <cstdint>

constexpr int B_ = 64, C_ = 512, NE_ = 80, NI_ = 20, E_ = 512;
#define DTC 0.1f

// bf16 stage: A [64 x 32] + W [80 x 32], row stride 80 bytes.
constexpr int LDB     = 80;
constexpr int A_BYTES = 64 * LDB;           // 5120
constexpr int W_BYTES = 80 * LDB;           // 6400
constexpr int STAGE_B = A_BYTES + W_BYTES;  // 11520
constexpr int NSTAGE  = 6;
constexpr int LDWEI   = 96;                 // W_ei f32 rows, cols 80..95 zero
constexpr int WEI_OFF = NSTAGE * STAGE_B;             // 69120
constexpr int SMEM_BYTES = WEI_OFF + 20 * LDWEI * 4;  // 76800 -> 2 CTAs/SM

constexpr size_t OFF_RI = (size_t)B_ * C_ * NE_;
constexpr size_t OFF_VE = OFF_RI + (size_t)B_ * C_ * NI_;
constexpr size_t OFF_VI = OFF_VE + (size_t)B_ * C_ * NE_;

// named barriers: FULL(s) = 1+s, EMPTY(s) = 7+s  (s in 0..5)
#define BAR_SYNC(id)   asm volatile("bar.sync %0, 256;"   :: "r"(id) : "memory")
#define BAR_ARRIVE(id) asm volatile("bar.arrive %0, 256;" :: "r"(id) : "memory")

__device__ __forceinline__ uint32_t s2u(const void* p) {
    uint32_t a;
    asm("{ .reg .u64 t; cvta.to.shared.u64 t, %1; cvt.u32.u64 %0, t; }" : "=r"(a) : "l"(p));
    return a;
}
__device__ __forceinline__ uint32_t bfx2(float2 f) {
    uint32_t r;
    asm("cvt.rn.bf16x2.f32 %0, %1, %2;" : "=r"(r) : "f"(f.y), "f"(f.x));
    return r;
}
__device__ __forceinline__ void sts_bf(uint32_t addr, float4 v) {
    uint32_t lo = bfx2(make_float2(v.x, v.y));
    uint32_t hi = bfx2(make_float2(v.z, v.w));
    asm volatile("st.shared.v2.b32 [%0], {%1,%2};" :: "r"(addr), "r"(lo), "r"(hi));
}
__device__ __forceinline__ void ldsm4(uint32_t r[4], uint32_t addr) {
    asm volatile("ldmatrix.sync.aligned.m8n8.x4.shared.b16 {%0,%1,%2,%3}, [%4];"
        : "=r"(r[0]), "=r"(r[1]), "=r"(r[2]), "=r"(r[3]) : "r"(addr));
}
__device__ __forceinline__ void mma16(float d[4], uint32_t a0, uint32_t a1,
                                      uint32_t a2, uint32_t a3,
                                      uint32_t b0, uint32_t b1) {
    asm("mma.sync.aligned.m16n8k16.row.col.f32.bf16.bf16.f32 "
        "{%0,%1,%2,%3}, {%4,%5,%6,%7}, {%8,%9}, {%0,%1,%2,%3};"
        : "+f"(d[0]), "+f"(d[1]), "+f"(d[2]), "+f"(d[3])
        : "r"(a0), "r"(a1), "r"(a2), "r"(a3), "r"(b0), "r"(b1));
}

// producer staging: 4 A float4s + 5 W float4s per thread (128 producer threads)
struct St { float4 a[4]; float4 wv[5]; };

// chunk table:
// ci 0-15 : I_ext k0=ci*32 (A=thal_inc, W=input_proj)
// ci 16-18: I_fb  k0=(ci-16)*32 (A=l23_fb, W=feedback_proj; k>=80 zero)
// ci 19-21: I_ee  k0=(ci-19)*32 (A=r_e, W=W_ee; k>=80 zero) + I_ei via Wei
// ci 22   : I_ie  K=20 pad 32 (A=r_i negated at cvt, W=W_ie)
__device__ __forceinline__ void load_p(
    int ci, int c, int p, St& s,
    const float* thal_inc, const float* l23_fb, const float* r_e,
    const float* r_i, const float* input_proj, const float* feedback_proj,
    const float* W_ee, const float* W_ie) {
    const float4 z = make_float4(0.f, 0.f, 0.f, 0.f);
    if (ci < 16) {
        const int k0 = ci * 32;
#pragma unroll
        for (int i = 0; i < 4; i++) {
            int idx = p + 128 * i, row = idx >> 3, g = idx & 7;
            s.a[i] = __ldg((const float4*)(thal_inc + ((size_t)row * C_ + c) * E_ + k0 + g * 4));
        }
#pragma unroll
        for (int i = 0; i < 5; i++) {
            int idx = p + 128 * i, row = idx >> 3, g = idx & 7;
            s.wv[i] = __ldg((const float4*)(input_proj + ((size_t)c * NE_ + row) * E_ + k0 + g * 4));
        }
    } else if (ci < 22) {
        const bool isB = ci < 19;
        const int col0 = (ci - (isB ? 16 : 19)) * 32;
        const float* Ap = isB ? l23_fb : r_e;
        const float* Wp = isB ? feedback_proj : W_ee;
#pragma unroll
        for (int i = 0; i < 4; i++) {
            int idx = p + 128 * i, row = idx >> 3, g = idx & 7, col = col0 + g * 4;
            s.a[i] = (col < NE_) ? __ldg((const float4*)(Ap + ((size_t)row * C_ + c) * NE_ + col)) : z;
        }
#pragma unroll
        for (int i = 0; i < 5; i++) {
            int idx = p + 128 * i, row = idx >> 3, g = idx & 7, col = col0 + g * 4;
            s.wv[i] = (col < NE_) ? __ldg((const float4*)(Wp + ((size_t)c * NE_ + row) * NE_ + col)) : z;
        }
    } else {
#pragma unroll
        for (int i = 0; i < 4; i++) {
            int idx = p + 128 * i, row = idx >> 3, g = idx & 7;
            s.a[i] = (g < 5) ? __ldg((const float4*)(r_i + ((size_t)row * C_ + c) * NI_ + g * 4)) : z;
        }
#pragma unroll
        for (int i = 0; i < 5; i++) {
            int idx = p + 128 * i, row = idx >> 3, g = idx & 7;
            s.wv[i] = (g < 5) ? __ldg((const float4*)(W_ie + ((size_t)c * NE_ + row) * NI_ + g * 4)) : z;
        }
    }
}

__device__ __forceinline__ void cvt_sts_p(int ci, int p, const St& s,
                                          uint32_t smb, const float* thal) {
    const uint32_t base = smb + (ci % NSTAGE) * STAGE_B;
#pragma unroll
    for (int i = 0; i < 4; i++) {
        int idx = p + 128 * i, row = idx >> 3, g = idx & 7;
        float4 a = s.a[i];
        if (ci < 16) {
            float4 th = __ldg((const float4*)(thal + (size_t)row * E_ + ci * 32 + g * 4));
            a.x += th.x; a.y += th.y; a.z += th.z; a.w += th.w;
        } else if (ci == 22) {
            a.x = -a.x; a.y = -a.y; a.z = -a.z; a.w = -a.w;
        }
        sts_bf(base + row * LDB + g * 8, a);
    }
#pragma unroll
    for (int i = 0; i < 5; i++) {
        int idx = p + 128 * i, row = idx >> 3, g = idx & 7;
        sts_bf(base + A_BYTES + row * LDB + g * 8, s.wv[i]);
    }
}

__global__ void __launch_bounds__(256, 2)
ei_ws(const float* __restrict__ thal, const float* __restrict__ thal_inc,
      const float* __restrict__ l23_fb, const float* __restrict__ r_e,
      const float* __restrict__ r_i, const float* __restrict__ e_v,
      const float* __restrict__ i_v, const float* __restrict__ input_proj,
      const float* __restrict__ feedback_proj, const float* __restrict__ W_ee,
      const float* __restrict__ W_ei, const float* __restrict__ W_ie,
      float* __restrict__ out) {
    extern __shared__ char smp[];
    const uint32_t smb = s2u(smp);
    const int t = threadIdx.x, c = blockIdx.x;
    const int w = t >> 5, lane = t & 31;

    if (w >= 4) {
        // ================= PRODUCER (warps 4-7) =================
        const int p = t - 128;
        // persistent W_ei f32 buffer (20 rows x 96, cols >=80 zero)
        for (int idx = p; idx < 480; idx += 128) {
            int row = idx / 24, g = idx % 24;
            float4 v = make_float4(0.f, 0.f, 0.f, 0.f);
            if (g < 20) v = __ldg((const float4*)(W_ei + ((size_t)c * NI_ + row) * NE_ + g * 4));
            *(float4*)(smp + WEI_OFF + (row * LDWEI + g * 4) * 4) = v;
        }
        St s0, s1;
        load_p(0, c, p, s0, thal_inc, l23_fb, r_e, r_i, input_proj, feedback_proj, W_ee, W_ie);
        load_p(1, c, p, s1, thal_inc, l23_fb, r_e, r_i, input_proj, feedback_proj, W_ee, W_ie);
#pragma unroll 1
        for (int ci = 0; ci < 23; ci++) {
            St& cur = (ci & 1) ? s1 : s0;
            if (ci >= NSTAGE) BAR_SYNC(7 + ci % NSTAGE);   // wait slot empty
            cvt_sts_p(ci, p, cur, smb, thal);
            asm volatile("membar.cta;" ::: "memory");
            BAR_ARRIVE(1 + ci % NSTAGE);                   // mark slot full
            if (ci + 2 < 23)
                load_p(ci + 2, c, p, cur, thal_inc, l23_fb, r_e, r_i,
                       input_proj, feedback_proj, W_ee, W_ie);
        }
        return;
    }

    // ================= CONSUMER (warps 0-3) =================
    const int wm = w, m0 = wm * 16;
    const int lm = lane >> 2, lc = lane & 3;

    float accE[10][4], accI[3][4];
#pragma unroll
    for (int j = 0; j < 10; j++)
#pragma unroll
        for (int q = 0; q < 4; q++) accE[j][q] = 0.f;
#pragma unroll
    for (int j = 0; j < 3; j++)
#pragma unroll
        for (int q = 0; q < 4; q++) accI[j][q] = 0.f;

    const float* Wei = (const float*)(smp + WEI_OFF);
    const bool wiv2 = (lm < 4);

    const uint32_t a_off = (uint32_t)((m0 + (lane & 7) + ((lane >> 3) & 1) * 8) * LDB
                                      + (lane >> 4) * 16);
    const uint32_t w_off = (uint32_t)(A_BYTES + (lane & 7) * LDB + (lane >> 3) * 16);

#pragma unroll 1
    for (int ci = 0; ci < 23; ci++) {
        BAR_SYNC(1 + ci % NSTAGE);                         // wait slot full
        const uint32_t base = smb + (ci % NSTAGE) * STAGE_B;
        uint32_t Ak0[4], Ak1[4];
        ldsm4(Ak0, base + a_off);
        ldsm4(Ak1, base + a_off + 32);
#pragma unroll
        for (int j = 0; j < 10; j++) {
            uint32_t Bf[4];
            ldsm4(Bf, base + w_off + (uint32_t)(j * 8 * LDB));
            mma16(accE[j], Ak0[0], Ak0[1], Ak0[2], Ak0[3], Bf[0], Bf[1]);
            mma16(accE[j], Ak1[0], Ak1[1], Ak1[2], Ak1[3], Bf[2], Bf[3]);
        }
        if (ci >= 19 && ci <= 21) {
            const int kei0 = (ci - 19) * 32;
            const float2 z = make_float2(0.f, 0.f);
#pragma unroll
            for (int j = 0; j < 3; j++) {
                const bool v = (j < 2) || wiv2;
                const float* wp = Wei + (j * 8 + (v ? lm : 0)) * LDWEI + kei0 + 2 * lc;
                uint32_t b0 = bfx2(v ? *(const float2*)(wp) : z);
                uint32_t b1 = bfx2(v ? *(const float2*)(wp + 8) : z);
                mma16(accI[j], Ak0[0], Ak0[1], Ak0[2], Ak0[3], b0, b1);
                uint32_t b2 = bfx2(v ? *(const float2*)(wp + 16) : z);
                uint32_t b3 = bfx2(v ? *(const float2*)(wp + 24) : z);
                mma16(accI[j], Ak1[0], Ak1[1], Ak1[2], Ak1[3], b2, b3);
            }
        }
        BAR_ARRIVE(7 + ci % NSTAGE);                       // mark slot empty
    }

    // ---------------- epilogue: leaky integration + relu ----------------
    const int r0 = m0 + lm, r1 = r0 + 8;
#pragma unroll
    for (int j = 0; j < 10; j++) {
        const int col = j * 8 + 2 * lc;
        const size_t i0 = ((size_t)r0 * C_ + c) * NE_ + col;
        const size_t i1 = ((size_t)r1 * C_ + c) * NE_ + col;
        float2 ev0 = *(const float2*)(e_v + i0);
        float2 ev1 = *(const float2*)(e_v + i1);
        float v0x = ev0.x + DTC * (accE[j][0] - ev0.x);
        float v0y = ev0.y + DTC * (accE[j][1] - ev0.y);
        float v1x = ev1.x + DTC * (accE[j][2] - ev1.x);
        float v1y = ev1.y + DTC * (accE[j][3] - ev1.y);
        *(float2*)(out + i0)          = make_float2(fmaxf(v0x, 0.f), fmaxf(v0y, 0.f));
        *(float2*)(out + i1)          = make_float2(fmaxf(v1x, 0.f), fmaxf(v1y, 0.f));
        *(float2*)(out + OFF_VE + i0) = make_float2(v0x, v0y);
        *(float2*)(out + OFF_VE + i1) = make_float2(v1x, v1y);
    }
#pragma unroll
    for (int j = 0; j < 3; j++) {
        const int col = j * 8 + 2 * lc;
        if (col < NI_) {
            const size_t i0 = ((size_t)r0 * C_ + c) * NI_ + col;
            const size_t i1 = ((size_t)r1 * C_ + c) * NI_ + col;
            float2 iv0 = *(const float2*)(i_v + i0);
            float2 iv1 = *(const float2*)(i_v + i1);
            float v0x = iv0.x + DTC * (accI[j][0] - iv0.x);
            float v0y = iv0.y + DTC * (accI[j][1] - iv0.y);
            float v1x = iv1.x + DTC * (accI[j][2] - iv1.x);
            float v1y = iv1.y + DTC * (accI[j][3] - iv1.y);
            *(float2*)(out + OFF_RI + i0) = make_float2(fmaxf(v0x, 0.f), fmaxf(v0y, 0.f));
            *(float2*)(out + OFF_RI + i1) = make_float2(fmaxf(v1x, 0.f), fmaxf(v1y, 0.f));
            *(float2*)(out + OFF_VI + i0) = make_float2(v0x, v0y);
            *(float2*)(out + OFF_VI + i1) = make_float2(v1x, v1y);
        }
    }
}

extern "C" void kernel_launch(void* const* d_in, const int* in_sizes, int n_in,
                              void* d_out, int out_size) {
    (void)in_sizes; (void)n_in; (void)out_size;
    cudaFuncSetAttribute(ei_ws, cudaFuncAttributeMaxDynamicSharedMemorySize,
                         SMEM_BYTES);
    ei_ws<<<C_, 256, SMEM_BYTES>>>(
        (const float*)d_in[0],   // thal
        (const float*)d_in[1],   // thal_increments
        (const float*)d_in[2],   // l23_fb
        (const float*)d_in[3],   // r_e
        (const float*)d_in[4],   // r_i
        (const float*)d_in[5],   // e_v
        (const float*)d_in[6],   // i_v
        (const float*)d_in[7],   // input_proj
        (const float*)d_in[8],   // feedback_proj
        (const float*)d_in[9],   // W_ee
        (const float*)d_in[10],  // W_ei
        (const float*)d_in[11],  // W_ie
        (float*)d_out);
}

// round 13
// speedup vs baseline: 1.8731x; 1.8731x over previous
#include <cuda_runtime.h>
#include <cstdint>

constexpr int B_ = 64, C_ = 512, NE_ = 80, NI_ = 20, E_ = 512;
#define DTC 0.1f

// f32 staging ring: A [64 x 32] + W [80 x 32] per slot, stride 40 floats.
constexpr int LDSF     = 40;
constexpr int F32_SLOT = (64 + 80) * LDSF * 4;   // 23040 B
constexpr int NF       = 3;
// bf16 mma ring: A [64 x 32] + W [80 x 32], row stride 80 bytes.
constexpr int LDB      = 80;
constexpr int A_BYTES  = 64 * LDB;               // 5120
constexpr int BF_SLOT  = A_BYTES + 80 * LDB;     // 11520
constexpr int BF_OFF   = NF * F32_SLOT;          // 69120
// persistent W_ei f32: 20 rows x 96 (cols 80..95 zero)
constexpr int LDWEI    = 96;
constexpr int WEI_OFF  = BF_OFF + 2 * BF_SLOT;   // 92160
constexpr int SMEM_BYTES = WEI_OFF + 20 * LDWEI * 4;  // 99840 -> 2 CTAs/SM

constexpr size_t OFF_RI = (size_t)B_ * C_ * NE_;
constexpr size_t OFF_VE = OFF_RI + (size_t)B_ * C_ * NI_;
constexpr size_t OFF_VI = OFF_VE + (size_t)B_ * C_ * NE_;

// ---------------- helpers ----------------
__device__ __forceinline__ uint32_t s2u(const void* p) {
    uint32_t a;
    asm("{ .reg .u64 t; cvta.to.shared.u64 t, %1; cvt.u32.u64 %0, t; }" : "=r"(a) : "l"(p));
    return a;
}
__device__ __forceinline__ void cpa16(uint32_t dst, const float* src) {
    asm volatile("cp.async.cg.shared.global [%0], [%1], 16;" :: "r"(dst), "l"(src));
}
__device__ __forceinline__ void cpa16z(uint32_t dst, const float* src) {
    asm volatile("cp.async.cg.shared.global [%0], [%1], 16, 0;" :: "r"(dst), "l"(src));
}
#define CP_COMMIT() asm volatile("cp.async.commit_group;" ::: "memory")
#define CP_WAIT2()  asm volatile("cp.async.wait_group 2;" ::: "memory")

__device__ __forceinline__ uint32_t bfx2(float2 f) {
    uint32_t r;
    asm("cvt.rn.bf16x2.f32 %0, %1, %2;" : "=r"(r) : "f"(f.y), "f"(f.x));
    return r;
}
__device__ __forceinline__ void sts_bf(uint32_t addr, float4 v) {
    uint32_t lo = bfx2(make_float2(v.x, v.y));
    uint32_t hi = bfx2(make_float2(v.z, v.w));
    asm volatile("st.shared.v2.b32 [%0], {%1,%2};" :: "r"(addr), "r"(lo), "r"(hi));
}
__device__ __forceinline__ void ldsm4(uint32_t r[4], uint32_t addr) {
    asm volatile("ldmatrix.sync.aligned.m8n8.x4.shared.b16 {%0,%1,%2,%3}, [%4];"
        : "=r"(r[0]), "=r"(r[1]), "=r"(r[2]), "=r"(r[3]) : "r"(addr));
}
__device__ __forceinline__ void mma16(float d[4], uint32_t a0, uint32_t a1,
                                      uint32_t a2, uint32_t a3,
                                      uint32_t b0, uint32_t b1) {
    asm("mma.sync.aligned.m16n8k16.row.col.f32.bf16.bf16.f32 "
        "{%0,%1,%2,%3}, {%4,%5,%6,%7}, {%8,%9}, {%0,%1,%2,%3};"
        : "+f"(d[0]), "+f"(d[1]), "+f"(d[2]), "+f"(d[3])
        : "r"(a0), "r"(a1), "r"(a2), "r"(a3), "r"(b0), "r"(b1));
}

// chunk table:
// ci 0-15 : I_ext k0=ci*32 (A=thal_inc, W=input_proj)
// ci 16-18: I_fb  k0=(ci-16)*32 (A=l23_fb, W=feedback_proj; cols>=80 zero)
// ci 19-21: I_ee  k0=(ci-19)*32 (A=r_e, W=W_ee; cols>=80 zero) + I_ei via Wei
// ci 22   : I_ie  K=20 pad 32 (A=r_i negated at cvt, W=W_ie)
// Per-thread mapping (256 threads): A float4s idx = t, t+256 -> row=idx>>3,
// g=idx&7.  W float4s idx = t, t+256, t+512(<640).  cvt reads back the SAME
// addresses this thread cp.async'd -> wait_group alone suffices (no barrier).
__device__ __forceinline__ void cpa_chunk(
    int ci, int c, int t, uint32_t smb,
    const float* thal_inc, const float* l23_fb, const float* r_e,
    const float* r_i, const float* input_proj, const float* feedback_proj,
    const float* W_ee, const float* W_ie) {
    const uint32_t fb = smb + (ci % NF) * F32_SLOT;
    if (ci < 16) {
        const int k0 = ci * 32;
#pragma unroll
        for (int i = 0; i < 2; i++) {
            int idx = t + 256 * i, row = idx >> 3, g = idx & 7;
            cpa16(fb + (row * LDSF + g * 4) * 4,
                  thal_inc + ((size_t)row * C_ + c) * E_ + k0 + g * 4);
        }
#pragma unroll
        for (int i = 0; i < 3; i++) {
            int idx = t + 256 * i;
            if (idx < 640) {
                int row = idx >> 3, g = idx & 7;
                cpa16(fb + ((64 + row) * LDSF + g * 4) * 4,
                      input_proj + ((size_t)c * NE_ + row) * E_ + k0 + g * 4);
            }
        }
    } else if (ci < 22) {
        const bool isB = ci < 19;
        const int k0 = (ci - (isB ? 16 : 19)) * 32;
        const float* Ap = isB ? l23_fb : r_e;
        const float* Wp = isB ? feedback_proj : W_ee;
#pragma unroll
        for (int i = 0; i < 2; i++) {
            int idx = t + 256 * i, row = idx >> 3, g = idx & 7, col = k0 + g * 4;
            uint32_t dst = fb + (row * LDSF + g * 4) * 4;
            const float* src = Ap + ((size_t)row * C_ + c) * NE_;
            if (col < NE_) cpa16(dst, src + col); else cpa16z(dst, src);
        }
#pragma unroll
        for (int i = 0; i < 3; i++) {
            int idx = t + 256 * i;
            if (idx < 640) {
                int row = idx >> 3, g = idx & 7, col = k0 + g * 4;
                uint32_t dst = fb + ((64 + row) * LDSF + g * 4) * 4;
                const float* src = Wp + ((size_t)c * NE_ + row) * NE_;
                if (col < NE_) cpa16(dst, src + col); else cpa16z(dst, src);
            }
        }
    } else {
#pragma unroll
        for (int i = 0; i < 2; i++) {
            int idx = t + 256 * i, row = idx >> 3, g = idx & 7;
            uint32_t dst = fb + (row * LDSF + g * 4) * 4;
            const float* src = r_i + ((size_t)row * C_ + c) * NI_;
            if (g < 5) cpa16(dst, src + g * 4); else cpa16z(dst, src);
        }
#pragma unroll
        for (int i = 0; i < 3; i++) {
            int idx = t + 256 * i;
            if (idx < 640) {
                int row = idx >> 3, g = idx & 7;
                uint32_t dst = fb + ((64 + row) * LDSF + g * 4) * 4;
                const float* src = W_ie + ((size_t)c * NE_ + row) * NI_;
                if (g < 5) cpa16(dst, src + g * 4); else cpa16z(dst, src);
            }
        }
    }
}

// f32 smem -> (thal fold / negate) -> bf16 smem. Same-thread readback.
__device__ __forceinline__ void cvt_chunk(int ci, int t, char* smp, uint32_t smb,
                                          const float* thal) {
    const char* fsrc = smp + (ci % NF) * F32_SLOT;
    const uint32_t bb = smb + BF_OFF + (ci & 1) * BF_SLOT;
#pragma unroll
    for (int i = 0; i < 2; i++) {
        int idx = t + 256 * i, row = idx >> 3, g = idx & 7;
        float4 a = *(const float4*)(fsrc + (row * LDSF + g * 4) * 4);
        if (ci < 16) {
            float4 th = __ldg((const float4*)(thal + (size_t)row * E_ + ci * 32 + g * 4));
            a.x += th.x; a.y += th.y; a.z += th.z; a.w += th.w;
        } else if (ci == 22) {
            a.x = -a.x; a.y = -a.y; a.z = -a.z; a.w = -a.w;
        }
        sts_bf(bb + row * LDB + g * 8, a);
    }
#pragma unroll
    for (int i = 0; i < 3; i++) {
        int idx = t + 256 * i;
        if (idx < 640) {
            int row = idx >> 3, g = idx & 7;
            float4 v = *(const float4*)(fsrc + ((64 + row) * LDSF + g * 4) * 4);
            sts_bf(bb + A_BYTES + row * LDB + g * 8, v);
        }
    }
}

__global__ void __launch_bounds__(256, 2)
ei_cpc(const float* __restrict__ thal, const float* __restrict__ thal_inc,
       const float* __restrict__ l23_fb, const float* __restrict__ r_e,
       const float* __restrict__ r_i, const float* __restrict__ e_v,
       const float* __restrict__ i_v, const float* __restrict__ input_proj,
       const float* __restrict__ feedback_proj, const float* __restrict__ W_ee,
       const float* __restrict__ W_ei, const float* __restrict__ W_ie,
       float* __restrict__ out) {
    extern __shared__ char smp[];
    const uint32_t smb = s2u(smp);
    const int t = threadIdx.x, c = blockIdx.x;
    const int w = t >> 5, lane = t & 31;
    const int wm = w >> 1, wn = w & 1;
    const int m0 = wm * 16, lm = lane >> 2, lc = lane & 3;

    float accE[5][4], accI[3][4];
#pragma unroll
    for (int j = 0; j < 5; j++)
#pragma unroll
        for (int q = 0; q < 4; q++) accE[j][q] = 0.f;
#pragma unroll
    for (int j = 0; j < 3; j++)
#pragma unroll
        for (int q = 0; q < 4; q++) accI[j][q] = 0.f;

    // ---- persistent W_ei f32 buffer (20 rows x 96, cols >=80 zero) ----
    for (int idx = t; idx < 480; idx += 256) {
        int row = idx / 24, g = idx % 24;
        float4 v = make_float4(0.f, 0.f, 0.f, 0.f);
        if (g < 20) v = __ldg((const float4*)(W_ei + ((size_t)c * NI_ + row) * NE_ + g * 4));
        *(float4*)(smp + WEI_OFF + (row * LDWEI + g * 4) * 4) = v;
    }
    const float* Wei = (const float*)(smp + WEI_OFF);
    const bool wiv2 = (lm < 4);

    const uint32_t a_off = (uint32_t)((m0 + (lane & 7) + ((lane >> 3) & 1) * 8) * LDB
                                      + (lane >> 4) * 16);
    const uint32_t w_off = (uint32_t)(A_BYTES + (wn * 40 + (lane & 7)) * LDB
                                      + (lane >> 3) * 16);

    auto compute = [&](int ci) {
        const uint32_t base = smb + BF_OFF + (ci & 1) * BF_SLOT;
        uint32_t Ak0[4], Ak1[4];
        ldsm4(Ak0, base + a_off);
        ldsm4(Ak1, base + a_off + 32);
#pragma unroll
        for (int j = 0; j < 5; j++) {
            uint32_t Bf[4];
            ldsm4(Bf, base + w_off + (uint32_t)(j * 8 * LDB));
            mma16(accE[j], Ak0[0], Ak0[1], Ak0[2], Ak0[3], Bf[0], Bf[1]);
            mma16(accE[j], Ak1[0], Ak1[1], Ak1[2], Ak1[3], Bf[2], Bf[3]);
        }
        if (ci >= 19 && ci <= 21 && wn == 0) {
            const int kei0 = (ci - 19) * 32;
            const float2 z = make_float2(0.f, 0.f);
#pragma unroll
            for (int j = 0; j < 3; j++) {
                const bool v = (j < 2) || wiv2;
                const float* wp = Wei + (j * 8 + (v ? lm : 0)) * LDWEI + kei0 + 2 * lc;
                uint32_t b0 = bfx2(v ? *(const float2*)(wp) : z);
                uint32_t b1 = bfx2(v ? *(const float2*)(wp + 8) : z);
                mma16(accI[j], Ak0[0], Ak0[1], Ak0[2], Ak0[3], b0, b1);
                uint32_t b2 = bfx2(v ? *(const float2*)(wp + 16) : z);
                uint32_t b3 = bfx2(v ? *(const float2*)(wp + 24) : z);
                mma16(accI[j], Ak1[0], Ak1[1], Ak1[2], Ak1[3], b2, b3);
            }
        }
    };

    // ---- prologue: prime f32 ring with chunks 0,1,2; convert chunk 0 ----
    cpa_chunk(0, c, t, smb, thal_inc, l23_fb, r_e, r_i, input_proj, feedback_proj, W_ee, W_ie);
    CP_COMMIT();
    cpa_chunk(1, c, t, smb, thal_inc, l23_fb, r_e, r_i, input_proj, feedback_proj, W_ee, W_ie);
    CP_COMMIT();
    cpa_chunk(2, c, t, smb, thal_inc, l23_fb, r_e, r_i, input_proj, feedback_proj, W_ee, W_ie);
    CP_COMMIT();
    CP_WAIT2();                    // chunk 0 arrived (own data)
    cvt_chunk(0, t, smp, smb, thal);
    __syncthreads();               // bf16 slot 0 + Wei visible to all

    // ---- mainloop: cpa(ci+3) | compute(ci) | wait+cvt(ci+1) | sync ----
#pragma unroll 1
    for (int ci = 0; ci < 23; ci++) {
        if (ci + 3 < 23)
            cpa_chunk(ci + 3, c, t, smb, thal_inc, l23_fb, r_e, r_i,
                      input_proj, feedback_proj, W_ee, W_ie);
        CP_COMMIT();               // always commit: uniform group counting
        compute(ci);
        if (ci + 1 < 23) {
            CP_WAIT2();            // chunk ci+1 arrived (FIFO group retirement)
            cvt_chunk(ci + 1, t, smp, smb, thal);
        }
        __syncthreads();
    }

    // ---------------- epilogue: leaky integration + relu ----------------
    const int r0 = m0 + lm, r1 = r0 + 8;
#pragma unroll
    for (int j = 0; j < 5; j++) {
        const int col = wn * 40 + j * 8 + 2 * lc;
        const size_t i0 = ((size_t)r0 * C_ + c) * NE_ + col;
        const size_t i1 = ((size_t)r1 * C_ + c) * NE_ + col;
        float2 ev0 = *(const float2*)(e_v + i0);
        float2 ev1 = *(const float2*)(e_v + i1);
        float v0x = ev0.x + DTC * (accE[j][0] - ev0.x);
        float v0y = ev0.y + DTC * (accE[j][1] - ev0.y);
        float v1x = ev1.x + DTC * (accE[j][2] - ev1.x);
        float v1y = ev1.y + DTC * (accE[j][3] - ev1.y);
        *(float2*)(out + i0)          = make_float2(fmaxf(v0x, 0.f), fmaxf(v0y, 0.f));
        *(float2*)(out + i1)          = make_float2(fmaxf(v1x, 0.f), fmaxf(v1y, 0.f));
        *(float2*)(out + OFF_VE + i0) = make_float2(v0x, v0y);
        *(float2*)(out + OFF_VE + i1) = make_float2(v1x, v1y);
    }
    if (wn == 0) {
#pragma unroll
        for (int j = 0; j < 3; j++) {
            const int col = j * 8 + 2 * lc;
            if (col < NI_) {
                const size_t i0 = ((size_t)r0 * C_ + c) * NI_ + col;
                const size_t i1 = ((size_t)r1 * C_ + c) * NI_ + col;
                float2 iv0 = *(const float2*)(i_v + i0);
                float2 iv1 = *(const float2*)(i_v + i1);
                float v0x = iv0.x + DTC * (accI[j][0] - iv0.x);
                float v0y = iv0.y + DTC * (accI[j][1] - iv0.y);
                float v1x = iv1.x + DTC * (accI[j][2] - iv1.x);
                float v1y = iv1.y + DTC * (accI[j][3] - iv1.y);
                *(float2*)(out + OFF_RI + i0) = make_float2(fmaxf(v0x, 0.f), fmaxf(v0y, 0.f));
                *(float2*)(out + OFF_RI + i1) = make_float2(fmaxf(v1x, 0.f), fmaxf(v1y, 0.f));
                *(float2*)(out + OFF_VI + i0) = make_float2(v0x, v0y);
                *(float2*)(out + OFF_VI + i1) = make_float2(v1x, v1y);
            }
        }
    }
}

extern "C" void kernel_launch(void* const* d_in, const int* in_sizes, int n_in,
                              void* d_out, int out_size) {
    (void)in_sizes; (void)n_in; (void)out_size;
    cudaFuncSetAttribute(ei_cpc, cudaFuncAttributeMaxDynamicSharedMemorySize,
                         SMEM_BYTES);
    ei_cpc<<<C_, 256, SMEM_BYTES>>>(
        (const float*)d_in[0],   // thal
        (const float*)d_in[1],   // thal_increments
        (const float*)d_in[2],   // l23_fb
        (const float*)d_in[3],   // r_e
        (const float*)d_in[4],   // r_i
        (const float*)d_in[5],   // e_v
        (const float*)d_in[6],   // i_v
        (const float*)d_in[7],   // input_proj
        (const float*)d_in[8],   // feedback_proj
        (const float*)d_in[9],   // W_ee
        (const float*)d_in[10],  // W_ei
        (const float*)d_in[11],  // W_ie
        (float*)d_out);
}